// round 16
// baseline (speedup 1.0000x reference)
#include <cuda_runtime.h>
#include <cuda_fp16.h>
#include <cstdint>

#define N_OBS   50000
#define N_TOTAL 100000
#define F       64
#define P       16
#define H       256
#define G3      768        // 3*H
#define G6      1536       // fused hh output width
#define XK      1024       // F*P
#define TWO_LOG_LIK_C 1.8378770664093453f

// ---------------- scratch (static __device__ — no allocations) ----------------
__device__ __half g_X1 [(size_t)N_OBS * XK];
__device__ __half g_X2 [(size_t)N_OBS * XK];
__device__ __half g_Hg [(size_t)N_OBS * H];
__device__ __half g_W1ih[(size_t)G3 * XK];
__device__ __half g_W2ih[(size_t)G3 * XK];
__device__ __half g_Whh [(size_t)G6 * H];
__device__ float  g_bhh[G6];
__device__ __half g_GI1 [(size_t)N_OBS * G3];
__device__ __half g_GI2 [(size_t)N_OBS * G3];
__device__ __half g_GH12[(size_t)N_OBS * G6];

__device__ __forceinline__ float sigmoidf_(float x) {
    return __fdividef(1.0f, 1.0f + __expf(-x));
}

__device__ __forceinline__ uint32_t smem_u32(const void* p) {
    uint32_t a;
    asm("{ .reg .u64 t; cvta.to.shared.u64 t, %1; cvt.u32.u64 %0, t; }" : "=r"(a) : "l"(p));
    return a;
}

__device__ __forceinline__ uint32_t h2bits(__half2 v) {
    return *reinterpret_cast<uint32_t*>(&v);
}
__device__ __forceinline__ __half2 bits2h(uint32_t u) {
    return *reinterpret_cast<__half2*>(&u);
}
__device__ __forceinline__ __half2 shfl_xor_h2(__half2 v, int off) {
    uint32_t u = __shfl_xor_sync(0xFFFFFFFFu, h2bits(v), off);
    return bits2h(u);
}

// ---------------- Kernel 1: losses + fused GCN + prep feats (half2 math) ----------------
#define PR_WP1H 0
#define PR_WP2H (PR_WP1H + 2048)
#define PR_BPH  (PR_WP2H + 2560)
#define PR_ADJ  (PR_BPH + 512)
#define PR_XS   (PR_ADJ + F * 65)
#define PR_MEAN (PR_XS + F)
#define PR_LV   (PR_MEAN + F)
#define PR_ERR  (PR_LV + F)
#define PR_MS   (PR_ERR + F)
#define PR_HOB  (PR_MS + F)
#define PR_AXS  (PR_HOB + F)
#define PR_SS   (PR_AXS + F)
#define PR_XH2  (PR_SS + F)
#define PR_MH2  (PR_XH2 + F)
#define PR_LH2  (PR_MH2 + F)
#define PR_EH2  (PR_LH2 + F)
#define PR_HH2  (PR_EH2 + F)
#define PR_MSH2 (PR_HH2 + F)
#define PREP_SMEM ((PR_MSH2 + F) * 4)
#define PREP_ROWS 16

__global__ void __launch_bounds__(256) prep_kernel(
    const float* __restrict__ p_obs, const float* __restrict__ X_obs,
    const float* __restrict__ M_obs, const float* __restrict__ adj,
    const float* __restrict__ w_prep, const float* __restrict__ w_prep2,
    const float* __restrict__ bias_prep,
    const float* __restrict__ gw1, const float* __restrict__ gb1,
    const float* __restrict__ gw2, const float* __restrict__ gb2,
    float* __restrict__ losses_out)
{
    extern __shared__ uint32_t spw[];
    uint32_t* wp1h = spw + PR_WP1H;
    uint32_t* wp2h = spw + PR_WP2H;
    uint32_t* bph  = spw + PR_BPH;
    float* adj_s = (float*)(spw + PR_ADJ);
    float* xs    = (float*)(spw + PR_XS);
    float* means = (float*)(spw + PR_MEAN);
    float* lvs   = (float*)(spw + PR_LV);
    float* errs  = (float*)(spw + PR_ERR);
    float* ms    = (float*)(spw + PR_MS);
    float* hob   = (float*)(spw + PR_HOB);
    float* axs   = (float*)(spw + PR_AXS);
    float* ss    = (float*)(spw + PR_SS);
    uint32_t* xh2  = spw + PR_XH2;
    uint32_t* mh2  = spw + PR_MH2;
    uint32_t* lh2  = spw + PR_LH2;
    uint32_t* eh2  = spw + PR_EH2;
    uint32_t* hh2  = spw + PR_HH2;
    uint32_t* msh2 = spw + PR_MSH2;

    const int t = threadIdx.x;

    for (int i = t; i < 2048; i += 256) {
        int k = i >> 9, r = i & 511, f = r >> 3, p2 = r & 7;
        int s0 = f * 64 + k * 16 + 2 * p2;
        wp1h[i] = h2bits(__floats2half2_rn(w_prep[s0], w_prep[s0 + 1]));
    }
    for (int i = t; i < 2560; i += 256) {
        int k = i >> 9, r = i & 511, f = r >> 3, p2 = r & 7;
        int s0 = f * 80 + k * 16 + 2 * p2;
        wp2h[i] = h2bits(__floats2half2_rn(w_prep2[s0], w_prep2[s0 + 1]));
    }
    for (int i = t; i < 512; i += 256) {
        int f = i >> 3, p2 = i & 7;
        int s0 = f * 16 + 2 * p2;
        bph[i] = h2bits(__floats2half2_rn(bias_prep[s0], bias_prep[s0 + 1]));
    }
    for (int i = t; i < F * F; i += 256)
        adj_s[(i >> 6) * 65 + (i & 63)] = adj[i];
    __syncthreads();

    const int fq   = t >> 2;
    const int part = t & 3;
    const float b2 = gb2[0];
    uint32_t* X1u = reinterpret_cast<uint32_t*>(g_X1);
    uint32_t* X2u = reinterpret_cast<uint32_t*>(g_X2);
    const __half2 zero2 = __float2half2_rn(0.0f);

    const int n0 = blockIdx.x * PREP_ROWS;
    for (int r = 0; r < PREP_ROWS; r++) {
        const int n = n0 + r;
        if (t < F) {
            const int f = t;
            float x    = X_obs[n * F + f];
            float mean = p_obs[n * (2 * F) + f];
            float lv   = p_obs[n * (2 * F) + F + f];
            float m    = M_obs[n * F + f];
            float err  = (x - mean) * __expf(-0.5f * lv);
            xs[f] = x; means[f] = mean; lvs[f] = lv; errs[f] = err; ms[f] = m;
            losses_out[n * F + f] = 0.5f * ((err * err + lv + TWO_LOG_LIK_C) * m);
        }
        __syncthreads();

        {
            const float* ar = adj_s + fq * 65;
            float a = 0.0f;
            #pragma unroll
            for (int g = part; g < F; g += 4) a = fmaf(ar[g], xs[g], a);
            a += __shfl_down_sync(0xFFFFFFFFu, a, 2, 4);
            a += __shfl_down_sync(0xFFFFFFFFu, a, 1, 4);
            if (part == 0) axs[fq] = a;
        }
        __syncthreads();
        if (t < F) {
            float a = axs[t];
            float s = 0.0f;
            #pragma unroll
            for (int c = 0; c < 32; c++) {
                float v = fmaf(a, gw1[c], gb1[c]);
                s = fmaf(gw2[c], fmaxf(v, 0.0f), s);
            }
            ss[t] = s;
        }
        __syncthreads();
        {
            const float* ar = adj_s + fq * 65;
            float a = 0.0f;
            #pragma unroll
            for (int g = part; g < F; g += 4) a = fmaf(ar[g], ss[g], a);
            a += __shfl_down_sync(0xFFFFFFFFu, a, 2, 4);
            a += __shfl_down_sync(0xFFFFFFFFu, a, 1, 4);
            if (part == 0) hob[fq] = a + b2;
        }
        __syncthreads();

        if (t < F) {
            xh2[t]  = h2bits(__float2half2_rn(xs[t]));
            mh2[t]  = h2bits(__float2half2_rn(means[t]));
            lh2[t]  = h2bits(__float2half2_rn(lvs[t]));
            eh2[t]  = h2bits(__float2half2_rn(errs[t]));
            hh2[t]  = h2bits(__float2half2_rn(hob[t]));
            msh2[t] = h2bits(__float2half2_rn(ms[t]));
        }
        __syncthreads();

        #pragma unroll
        for (int rep = 0; rep < 2; rep++) {
            const int i2 = t + rep * 256;
            const int f = i2 >> 3;
            __half2 v = bits2h(bph[i2]);
            v = __hfma2(bits2h(xh2[f]), bits2h(wp1h[i2]),        v);
            v = __hfma2(bits2h(mh2[f]), bits2h(wp1h[512 + i2]),  v);
            v = __hfma2(bits2h(lh2[f]), bits2h(wp1h[1024 + i2]), v);
            v = __hfma2(bits2h(eh2[f]), bits2h(wp1h[1536 + i2]), v);
            v = __hmul2(__hmax2(v, zero2), bits2h(msh2[f]));
            X1u[(size_t)n * 512 + i2] = h2bits(v);

            __half2 u = bits2h(bph[i2]);
            u = __hfma2(bits2h(xh2[f]), bits2h(wp2h[i2]),        u);
            u = __hfma2(bits2h(hh2[f]), bits2h(wp2h[512 + i2]),  u);
            u = __hfma2(bits2h(mh2[f]), bits2h(wp2h[1024 + i2]), u);
            u = __hfma2(bits2h(lh2[f]), bits2h(wp2h[1536 + i2]), u);
            u = __hfma2(bits2h(eh2[f]), bits2h(wp2h[2048 + i2]), u);
            u = __hmul2(__hmax2(u, zero2), bits2h(msh2[f]));
            X2u[(size_t)n * 512 + i2] = h2bits(u);
        }
        __syncthreads();
    }
}

// ---------------- fp32 -> fp16 convert and gather ----------------
__global__ void __launch_bounds__(256) convert_kernel(
    const float* __restrict__ src, __half* __restrict__ dst, int n)
{
    int i = blockIdx.x * 256 + threadIdx.x;
    if (i < n) dst[i] = __float2half(src[i]);
}

__global__ void __launch_bounds__(256) gather_kernel(
    const float* __restrict__ h, const int* __restrict__ i_obs,
    __half* __restrict__ dst)
{
    int n = blockIdx.x, t = threadIdx.x;
    int idx = i_obs[n];
    dst[(size_t)n * H + t] = __float2half(h[(size_t)idx * H + t]);
}

// ---------------- Kernel 2: HMMA fp16 GEMM, 4-stage ring, 2 CTAs/SM ----------------
#define BM 128
#define BN 128
#define BKB 32
#define PITCH 80
#define STAGE_MAT (BM * PITCH)
#define STAGE_BYTES (2 * STAGE_MAT)       // A, B = 20480
#define NSTAGE 4
#define GEMM_SMEM (NSTAGE * STAGE_BYTES)  // 81920; x2 CTAs = 163840 <= 228KB

__device__ __forceinline__ void cp16(uint32_t dst, const void* src, bool pred) {
    asm volatile("cp.async.cg.shared.global [%0], [%1], 16, %2;"
                 :: "r"(dst), "l"(src), "r"(pred ? 16 : 0));
}
__device__ __forceinline__ void ldm_x4(uint32_t* r, uint32_t addr) {
    asm volatile("ldmatrix.sync.aligned.m8n8.x4.shared.b16 {%0,%1,%2,%3}, [%4];"
                 : "=r"(r[0]), "=r"(r[1]), "=r"(r[2]), "=r"(r[3]) : "r"(addr));
}
__device__ __forceinline__ void mma16816(float* c, const uint32_t* a, uint32_t b0, uint32_t b1) {
    asm volatile("mma.sync.aligned.m16n8k16.row.col.f32.f16.f16.f32 "
                 "{%0,%1,%2,%3}, {%4,%5,%6,%7}, {%8,%9}, {%0,%1,%2,%3};"
                 : "+f"(c[0]), "+f"(c[1]), "+f"(c[2]), "+f"(c[3])
                 : "r"(a[0]), "r"(a[1]), "r"(a[2]), "r"(a[3]), "r"(b0), "r"(b1));
}

__global__ void __launch_bounds__(256, 2) mma_gemm(
    const __half* __restrict__ A, const __half* __restrict__ B,
    const float* __restrict__ bias, __half* __restrict__ C,
    int M, int K, int ldc)
{
    extern __shared__ char smem_raw[];
    const uint32_t su = smem_u32(smem_raw);

    const int t    = threadIdx.x;
    const int wid  = t >> 5;
    const int lane = t & 31;
    const int bm   = blockIdx.y * BM;
    const int bn   = blockIdx.x * BN;
    const int nk   = K / BKB;

    const int wm = (wid & 1) * 64;
    const int wn = (wid >> 1) * 32;

    const int rowt  = t >> 2;
    const int chunk = t & 3;

    const int garow0 = bm + rowt, garow1 = bm + rowt + 64;
    const bool p0 = garow0 < M, p1 = garow1 < M;
    const __half* A0 = A + (size_t)(p0 ? garow0 : 0) * K + chunk * 8;
    const __half* A1 = A + (size_t)(p1 ? garow1 : 0) * K + chunk * 8;
    const __half* B0 = B + (size_t)(bn + rowt) * K + chunk * 8;
    const __half* B1 = B + (size_t)(bn + rowt + 64) * K + chunk * 8;

    const uint32_t d0 = (uint32_t)rowt * PITCH + (uint32_t)chunk * 16;
    const uint32_t d1 = d0 + 64 * PITCH;

    auto load_stage = [&](int kb, int buf) {
        const uint32_t base = su + buf * STAGE_BYTES;
        const int ke = kb * BKB;
        cp16(base + d0,             A0 + ke, p0);
        cp16(base + d1,             A1 + ke, p1);
        cp16(base + STAGE_MAT + d0, B0 + ke, true);
        cp16(base + STAGE_MAT + d1, B1 + ke, true);
    };

    float acc[4][4][4];
    #pragma unroll
    for (int i = 0; i < 4; i++)
        #pragma unroll
        for (int j = 0; j < 4; j++)
            #pragma unroll
            for (int k = 0; k < 4; k++) acc[i][j][k] = 0.0f;

    // preload 3 stages, one commit each
    load_stage(0, 0); asm volatile("cp.async.commit_group;");
    load_stage(1, 1); asm volatile("cp.async.commit_group;");
    load_stage(2, 2); asm volatile("cp.async.commit_group;");

    int buf = 0;
    for (int kb = 0; kb < nk; kb++) {
        // uniform protocol: exactly one commit per iter (possibly empty),
        // wait_group 2 -> stage kb guaranteed complete
        asm volatile("cp.async.wait_group 2;");
        __syncthreads();

        const uint32_t sa = su + buf * STAGE_BYTES;
        const uint32_t sb = sa + STAGE_MAT;

        if (kb + 3 < nk) {
            int lbuf = buf + 3; if (lbuf >= NSTAGE) lbuf -= NSTAGE;
            load_stage(kb + 3, lbuf);
        }
        asm volatile("cp.async.commit_group;");

        #pragma unroll
        for (int ks = 0; ks < 2; ks++) {
            const uint32_t kbyte = (uint32_t)ks * 32;
            uint32_t a_r[4][4];
            const uint32_t arow = (uint32_t)(wm + (lane & 15)) * PITCH
                                + kbyte + ((uint32_t)(lane >> 4) << 4);
            #pragma unroll
            for (int mf = 0; mf < 4; mf++)
                ldm_x4(a_r[mf], sa + arow + (uint32_t)mf * 16 * PITCH);

            uint32_t b_r[2][4];
            const uint32_t brow = (uint32_t)(wn + (((lane >> 3) & 2) << 2) + (lane & 7)) * PITCH
                                + kbyte + (((uint32_t)(lane >> 3) & 1) << 4);
            #pragma unroll
            for (int nfp = 0; nfp < 2; nfp++)
                ldm_x4(b_r[nfp], sb + brow + (uint32_t)nfp * 16 * PITCH);

            #pragma unroll
            for (int mf = 0; mf < 4; mf++)
                #pragma unroll
                for (int nf = 0; nf < 4; nf++) {
                    const int nfp = nf >> 1, sub = (nf & 1) * 2;
                    mma16816(acc[mf][nf], a_r[mf], b_r[nfp][sub], b_r[nfp][sub + 1]);
                }
        }
        buf = buf + 1; if (buf >= NSTAGE) buf -= NSTAGE;
    }

    #pragma unroll
    for (int mf = 0; mf < 4; mf++) {
        const int r0 = bm + wm + mf * 16 + (lane >> 2);
        #pragma unroll
        for (int nf = 0; nf < 4; nf++) {
            const int col = bn + wn + nf * 8 + (lane & 3) * 2;
            const float b0 = bias[col], b1 = bias[col + 1];
            if (r0 < M)
                *(__half2*)(C + (size_t)r0 * ldc + col) =
                    __floats2half2_rn(acc[mf][nf][0] + b0, acc[mf][nf][1] + b1);
            if (r0 + 8 < M)
                *(__half2*)(C + (size_t)(r0 + 8) * ldc + col) =
                    __floats2half2_rn(acc[mf][nf][2] + b0, acc[mf][nf][3] + b1);
        }
    }
}

// ---------------- Kernel 3: GRU gates + MLP head, half2 math ----------------
#define GR 16
#define GW1H 0
#define GW3H (GW1H + 32 * 256)
#define GW2S (GW3H + 256 * 17)
#define GZIN (GW2S + 32 * 33)
#define GZ1  (GZIN + 256)
#define GZ2H (GZ1 + 32)
#define GB1S (GZ2H + 16)
#define GB2S (GB1S + 32)
#define GB3S (GB2S + 32)
#define GATES_SMEM ((GB3S + 256) * 4)

__global__ void __launch_bounds__(256) gates_mlp_kernel(
    const float* __restrict__ h, const int* __restrict__ i_obs,
    const float* __restrict__ m_w1, const float* __restrict__ m_b1,
    const float* __restrict__ m_w2, const float* __restrict__ m_b2,
    const float* __restrict__ m_w3, const float* __restrict__ m_b3,
    float* __restrict__ out_h)
{
    extern __shared__ uint32_t smu[];
    uint32_t* w1h = smu + GW1H;
    uint32_t* w3h = smu + GW3H;
    float*    w2s = (float*)(smu + GW2S);
    uint32_t* zin = smu + GZIN;
    __half*   zin_h = (__half*)zin;
    float*    z1  = (float*)(smu + GZ1);
    __half*   z2h = (__half*)(smu + GZ2H);
    uint32_t* z2u = smu + GZ2H;
    float*    b1s = (float*)(smu + GB1S);
    float*    b2s = (float*)(smu + GB2S);
    float*    b3s = (float*)(smu + GB3S);

    const int t    = threadIdx.x;
    const int wid  = t >> 5;
    const int lane = t & 31;

    for (int i = t; i < 32 * 256; i += 256)
        w1h[i] = h2bits(__floats2half2_rn(m_w1[2 * i], m_w1[2 * i + 1]));
    for (int i = t; i < 256 * 16; i += 256) {
        int o = i >> 4, k = i & 15;
        w3h[o * 17 + k] = h2bits(__floats2half2_rn(m_w3[2 * i], m_w3[2 * i + 1]));
    }
    for (int i = t; i < 32 * 32; i += 256)
        w2s[(i >> 5) * 33 + (i & 31)] = m_w2[i];
    if (t < 32) { b1s[t] = m_b1[t]; b2s[t] = m_b2[t]; }
    for (int i = t; i < 256; i += 256) b3s[i] = m_b3[i];
    __syncthreads();

    const int n0 = blockIdx.x * GR;
    for (int r = 0; r < GR; r++) {
        const int n = n0 + r;
        const int idx = i_obs[n];
        const size_t b  = (size_t)n * G3;
        const size_t bh = (size_t)n * G6;

        const float hg = h[(size_t)idx * H + t];
        {
            float gi0 = __half2float(g_GI1[b + t]);
            float gi1 = __half2float(g_GI1[b + H + t]);
            float gi2 = __half2float(g_GI1[b + 2 * H + t]);
            float gh0 = __half2float(g_GH12[bh + t]);
            float gh1 = __half2float(g_GH12[bh + H + t]);
            float gh2 = __half2float(g_GH12[bh + 2 * H + t]);
            float rr = sigmoidf_(gi0 + gh0);
            float zz = sigmoidf_(gi1 + gh1);
            float ng = tanhf(gi2 + rr * gh2);
            zin_h[t] = __float2half((1.0f - zz) * ng + zz * hg);
        }
        {
            float gi0 = __half2float(g_GI2[b + t]);
            float gi1 = __half2float(g_GI2[b + H + t]);
            float gi2 = __half2float(g_GI2[b + 2 * H + t]);
            float gh0 = __half2float(g_GH12[bh + G3 + t]);
            float gh1 = __half2float(g_GH12[bh + G3 + H + t]);
            float gh2 = __half2float(g_GH12[bh + G3 + 2 * H + t]);
            float rr = sigmoidf_(gi0 + gh0);
            float zz = sigmoidf_(gi1 + gh1);
            float ng = tanhf(gi2 + rr * gh2);
            zin_h[256 + t] = __float2half((1.0f - zz) * ng + zz * hg);
        }
        __syncthreads();

        uint32_t zr[8];
        #pragma unroll
        for (int j = 0; j < 8; j++) zr[j] = zin[lane + 32 * j];
        #pragma unroll
        for (int q = 0; q < 4; q++) {
            const int o = 4 * wid + q;
            const uint32_t* wr = w1h + o * 256;
            __half2 s2 = __float2half2_rn(0.0f);
            #pragma unroll
            for (int j = 0; j < 8; j++)
                s2 = __hfma2(bits2h(wr[lane + 32 * j]), bits2h(zr[j]), s2);
            #pragma unroll
            for (int off = 16; off > 0; off >>= 1)
                s2 = __hadd2(s2, shfl_xor_h2(s2, off));
            if (lane == 0) {
                float s = __low2float(s2) + __high2float(s2) + b1s[o];
                z1[o] = fmaxf(s, 0.0f);
            }
        }
        __syncthreads();

        if (t < 32) {
            const float* w = w2s + t * 33;
            float s = b2s[t];
            #pragma unroll
            for (int k = 0; k < 32; k++) s = fmaf(z1[k], w[k], s);
            z2h[t] = __float2half(fmaxf(s, 0.0f));
        }
        __syncthreads();

        {
            const uint32_t* wr = w3h + t * 17;
            __half2 s2 = __float2half2_rn(0.0f);
            #pragma unroll
            for (int k = 0; k < 16; k++)
                s2 = __hfma2(bits2h(wr[k]), bits2h(z2u[k]), s2);
            float s = __low2float(s2) + __high2float(s2) + b3s[t];
            out_h[(size_t)idx * H + t] = s * sigmoidf_(s);
        }
        __syncthreads();
    }
}

// ---------------- launch ----------------
extern "C" void kernel_launch(void* const* d_in, const int* in_sizes, int n_in,
                              void* d_out, int out_size)
{
    const float* h         = (const float*)d_in[0];
    const float* p_obs     = (const float*)d_in[1];
    const float* X_obs     = (const float*)d_in[2];
    const float* M_obs     = (const float*)d_in[3];
    const float* adj       = (const float*)d_in[4];
    const int*   i_obs     = (const int*)  d_in[5];
    const float* w_prep    = (const float*)d_in[6];
    const float* w_prep2   = (const float*)d_in[7];
    const float* bias_prep = (const float*)d_in[8];
    const float* g1_w_ih   = (const float*)d_in[9];
    const float* g1_w_hh   = (const float*)d_in[10];
    const float* g1_b_ih   = (const float*)d_in[11];
    const float* g1_b_hh   = (const float*)d_in[12];
    const float* g2_w_ih   = (const float*)d_in[13];
    const float* g2_w_hh   = (const float*)d_in[14];
    const float* g2_b_ih   = (const float*)d_in[15];
    const float* g2_b_hh   = (const float*)d_in[16];
    const float* gcn_w1    = (const float*)d_in[17];
    const float* gcn_b1    = (const float*)d_in[18];
    const float* gcn_w2    = (const float*)d_in[19];
    const float* gcn_b2    = (const float*)d_in[20];
    const float* m_w1      = (const float*)d_in[21];
    const float* m_b1      = (const float*)d_in[22];
    const float* m_w2      = (const float*)d_in[23];
    const float* m_b2      = (const float*)d_in[24];
    const float* m_w3      = (const float*)d_in[25];
    const float* m_b3      = (const float*)d_in[26];

    float* out_h      = (float*)d_out;                           // [100000,256]
    float* out_losses = (float*)d_out + (size_t)N_TOTAL * H;     // [50000,64]

    cudaMemcpyAsync(out_h, h, (size_t)N_TOTAL * H * sizeof(float),
                    cudaMemcpyDeviceToDevice, 0);

    __half *pX1, *pX2, *pHg, *pW1ih, *pW2ih, *pWhh, *pGI1, *pGI2, *pGH12;
    float *pbhh;
    cudaGetSymbolAddress((void**)&pX1, g_X1);
    cudaGetSymbolAddress((void**)&pX2, g_X2);
    cudaGetSymbolAddress((void**)&pHg, g_Hg);
    cudaGetSymbolAddress((void**)&pW1ih, g_W1ih);
    cudaGetSymbolAddress((void**)&pW2ih, g_W2ih);
    cudaGetSymbolAddress((void**)&pWhh, g_Whh);
    cudaGetSymbolAddress((void**)&pGI1, g_GI1);
    cudaGetSymbolAddress((void**)&pGI2, g_GI2);
    cudaGetSymbolAddress((void**)&pGH12, g_GH12);
    cudaGetSymbolAddress((void**)&pbhh, g_bhh);

    cudaMemcpyAsync(pbhh,      g1_b_hh, G3 * sizeof(float), cudaMemcpyDeviceToDevice, 0);
    cudaMemcpyAsync(pbhh + G3, g2_b_hh, G3 * sizeof(float), cudaMemcpyDeviceToDevice, 0);

    gather_kernel<<<N_OBS, 256>>>(h, i_obs, pHg);
    convert_kernel<<<(G3 * H + 255) / 256, 256>>>(g1_w_hh, pWhh, G3 * H);
    convert_kernel<<<(G3 * H + 255) / 256, 256>>>(g2_w_hh, pWhh + (size_t)G3 * H, G3 * H);

    cudaFuncSetAttribute(mma_gemm, cudaFuncAttributeMaxDynamicSharedMemorySize, GEMM_SMEM);

    dim3 gg_ih(G3 / 128, (N_OBS + 127) / 128);
    dim3 gg_hh(G6 / 128, (N_OBS + 127) / 128);
    mma_gemm<<<gg_hh, 256, GEMM_SMEM>>>(pHg, pWhh, pbhh, pGH12, N_OBS, H, G6);

    cudaFuncSetAttribute(prep_kernel, cudaFuncAttributeMaxDynamicSharedMemorySize, PREP_SMEM);
    prep_kernel<<<N_OBS / PREP_ROWS, 256, PREP_SMEM>>>(
        p_obs, X_obs, M_obs, adj, w_prep, w_prep2, bias_prep,
        gcn_w1, gcn_b1, gcn_w2, gcn_b2, out_losses);

    convert_kernel<<<(G3 * XK + 255) / 256, 256>>>(g1_w_ih, pW1ih, G3 * XK);
    convert_kernel<<<(G3 * XK + 255) / 256, 256>>>(g2_w_ih, pW2ih, G3 * XK);

    mma_gemm<<<gg_ih, 256, GEMM_SMEM>>>(pX1, pW1ih, g1_b_ih, pGI1, N_OBS, XK, G3);
    mma_gemm<<<gg_ih, 256, GEMM_SMEM>>>(pX2, pW2ih, g2_b_ih, pGI2, N_OBS, XK, G3);

    cudaFuncSetAttribute(gates_mlp_kernel, cudaFuncAttributeMaxDynamicSharedMemorySize, GATES_SMEM);
    gates_mlp_kernel<<<N_OBS / GR, 256, GATES_SMEM>>>(h, i_obs, m_w1, m_b1, m_w2, m_b2,
                                                      m_w3, m_b3, out_h);
}

// round 17
// speedup vs baseline: 1.4495x; 1.4495x over previous
#include <cuda_runtime.h>
#include <cuda_fp16.h>
#include <cstdint>

#define N_OBS   50000
#define N_TOTAL 100000
#define F       64
#define P       16
#define H       256
#define G3      768        // 3*H
#define G6      1536       // fused hh output width
#define XK      1024       // F*P
#define TWO_LOG_LIK_C 1.8378770664093453f

// ---------------- scratch (static __device__ — no allocations) ----------------
__device__ __half g_X1 [(size_t)N_OBS * XK];
__device__ __half g_X2 [(size_t)N_OBS * XK];
__device__ __half g_Hg [(size_t)N_OBS * H];
__device__ __half g_W1ih[(size_t)G3 * XK];
__device__ __half g_W2ih[(size_t)G3 * XK];
__device__ __half g_Whh [(size_t)G6 * H];
__device__ float  g_bhh[G6];
__device__ __half g_GI1 [(size_t)N_OBS * G3];
__device__ __half g_GI2 [(size_t)N_OBS * G3];
__device__ __half g_GH12[(size_t)N_OBS * G6];

__device__ __forceinline__ float sigmoidf_(float x) {
    return __fdividef(1.0f, 1.0f + __expf(-x));
}

__device__ __forceinline__ uint32_t smem_u32(const void* p) {
    uint32_t a;
    asm("{ .reg .u64 t; cvta.to.shared.u64 t, %1; cvt.u32.u64 %0, t; }" : "=r"(a) : "l"(p));
    return a;
}

__device__ __forceinline__ uint32_t h2bits(__half2 v) {
    return *reinterpret_cast<uint32_t*>(&v);
}
__device__ __forceinline__ __half2 bits2h(uint32_t u) {
    return *reinterpret_cast<__half2*>(&u);
}
__device__ __forceinline__ __half2 shfl_xor_h2(__half2 v, int off) {
    uint32_t u = __shfl_xor_sync(0xFFFFFFFFu, h2bits(v), off);
    return bits2h(u);
}

// ---------------- Kernel 1: losses + fused GCN + prep feats (half2 math) ----------------
#define PR_WP1H 0
#define PR_WP2H (PR_WP1H + 2048)
#define PR_BPH  (PR_WP2H + 2560)
#define PR_ADJ  (PR_BPH + 512)
#define PR_XS   (PR_ADJ + F * 65)
#define PR_MEAN (PR_XS + F)
#define PR_LV   (PR_MEAN + F)
#define PR_ERR  (PR_LV + F)
#define PR_MS   (PR_ERR + F)
#define PR_HOB  (PR_MS + F)
#define PR_AXS  (PR_HOB + F)
#define PR_SS   (PR_AXS + F)
#define PR_XH2  (PR_SS + F)
#define PR_MH2  (PR_XH2 + F)
#define PR_LH2  (PR_MH2 + F)
#define PR_EH2  (PR_LH2 + F)
#define PR_HH2  (PR_EH2 + F)
#define PR_MSH2 (PR_HH2 + F)
#define PREP_SMEM ((PR_MSH2 + F) * 4)
#define PREP_ROWS 16

__global__ void __launch_bounds__(256) prep_kernel(
    const float* __restrict__ p_obs, const float* __restrict__ X_obs,
    const float* __restrict__ M_obs, const float* __restrict__ adj,
    const float* __restrict__ w_prep, const float* __restrict__ w_prep2,
    const float* __restrict__ bias_prep,
    const float* __restrict__ gw1, const float* __restrict__ gb1,
    const float* __restrict__ gw2, const float* __restrict__ gb2,
    float* __restrict__ losses_out)
{
    extern __shared__ uint32_t spw[];
    uint32_t* wp1h = spw + PR_WP1H;
    uint32_t* wp2h = spw + PR_WP2H;
    uint32_t* bph  = spw + PR_BPH;
    float* adj_s = (float*)(spw + PR_ADJ);
    float* xs    = (float*)(spw + PR_XS);
    float* means = (float*)(spw + PR_MEAN);
    float* lvs   = (float*)(spw + PR_LV);
    float* errs  = (float*)(spw + PR_ERR);
    float* ms    = (float*)(spw + PR_MS);
    float* hob   = (float*)(spw + PR_HOB);
    float* axs   = (float*)(spw + PR_AXS);
    float* ss    = (float*)(spw + PR_SS);
    uint32_t* xh2  = spw + PR_XH2;
    uint32_t* mh2  = spw + PR_MH2;
    uint32_t* lh2  = spw + PR_LH2;
    uint32_t* eh2  = spw + PR_EH2;
    uint32_t* hh2  = spw + PR_HH2;
    uint32_t* msh2 = spw + PR_MSH2;

    const int t = threadIdx.x;

    for (int i = t; i < 2048; i += 256) {
        int k = i >> 9, r = i & 511, f = r >> 3, p2 = r & 7;
        int s0 = f * 64 + k * 16 + 2 * p2;
        wp1h[i] = h2bits(__floats2half2_rn(w_prep[s0], w_prep[s0 + 1]));
    }
    for (int i = t; i < 2560; i += 256) {
        int k = i >> 9, r = i & 511, f = r >> 3, p2 = r & 7;
        int s0 = f * 80 + k * 16 + 2 * p2;
        wp2h[i] = h2bits(__floats2half2_rn(w_prep2[s0], w_prep2[s0 + 1]));
    }
    for (int i = t; i < 512; i += 256) {
        int f = i >> 3, p2 = i & 7;
        int s0 = f * 16 + 2 * p2;
        bph[i] = h2bits(__floats2half2_rn(bias_prep[s0], bias_prep[s0 + 1]));
    }
    for (int i = t; i < F * F; i += 256)
        adj_s[(i >> 6) * 65 + (i & 63)] = adj[i];
    __syncthreads();

    const int fq   = t >> 2;
    const int part = t & 3;
    const float b2 = gb2[0];
    uint32_t* X1u = reinterpret_cast<uint32_t*>(g_X1);
    uint32_t* X2u = reinterpret_cast<uint32_t*>(g_X2);
    const __half2 zero2 = __float2half2_rn(0.0f);

    const int n0 = blockIdx.x * PREP_ROWS;
    for (int r = 0; r < PREP_ROWS; r++) {
        const int n = n0 + r;
        if (t < F) {
            const int f = t;
            float x    = X_obs[n * F + f];
            float mean = p_obs[n * (2 * F) + f];
            float lv   = p_obs[n * (2 * F) + F + f];
            float m    = M_obs[n * F + f];
            float err  = (x - mean) * __expf(-0.5f * lv);
            xs[f] = x; means[f] = mean; lvs[f] = lv; errs[f] = err; ms[f] = m;
            losses_out[n * F + f] = 0.5f * ((err * err + lv + TWO_LOG_LIK_C) * m);
        }
        __syncthreads();

        {
            const float* ar = adj_s + fq * 65;
            float a = 0.0f;
            #pragma unroll
            for (int g = part; g < F; g += 4) a = fmaf(ar[g], xs[g], a);
            a += __shfl_down_sync(0xFFFFFFFFu, a, 2, 4);
            a += __shfl_down_sync(0xFFFFFFFFu, a, 1, 4);
            if (part == 0) axs[fq] = a;
        }
        __syncthreads();
        if (t < F) {
            float a = axs[t];
            float s = 0.0f;
            #pragma unroll
            for (int c = 0; c < 32; c++) {
                float v = fmaf(a, gw1[c], gb1[c]);
                s = fmaf(gw2[c], fmaxf(v, 0.0f), s);
            }
            ss[t] = s;
        }
        __syncthreads();
        {
            const float* ar = adj_s + fq * 65;
            float a = 0.0f;
            #pragma unroll
            for (int g = part; g < F; g += 4) a = fmaf(ar[g], ss[g], a);
            a += __shfl_down_sync(0xFFFFFFFFu, a, 2, 4);
            a += __shfl_down_sync(0xFFFFFFFFu, a, 1, 4);
            if (part == 0) hob[fq] = a + b2;
        }
        __syncthreads();

        if (t < F) {
            xh2[t]  = h2bits(__float2half2_rn(xs[t]));
            mh2[t]  = h2bits(__float2half2_rn(means[t]));
            lh2[t]  = h2bits(__float2half2_rn(lvs[t]));
            eh2[t]  = h2bits(__float2half2_rn(errs[t]));
            hh2[t]  = h2bits(__float2half2_rn(hob[t]));
            msh2[t] = h2bits(__float2half2_rn(ms[t]));
        }
        __syncthreads();

        #pragma unroll
        for (int rep = 0; rep < 2; rep++) {
            const int i2 = t + rep * 256;
            const int f = i2 >> 3;
            __half2 v = bits2h(bph[i2]);
            v = __hfma2(bits2h(xh2[f]), bits2h(wp1h[i2]),        v);
            v = __hfma2(bits2h(mh2[f]), bits2h(wp1h[512 + i2]),  v);
            v = __hfma2(bits2h(lh2[f]), bits2h(wp1h[1024 + i2]), v);
            v = __hfma2(bits2h(eh2[f]), bits2h(wp1h[1536 + i2]), v);
            v = __hmul2(__hmax2(v, zero2), bits2h(msh2[f]));
            X1u[(size_t)n * 512 + i2] = h2bits(v);

            __half2 u = bits2h(bph[i2]);
            u = __hfma2(bits2h(xh2[f]), bits2h(wp2h[i2]),        u);
            u = __hfma2(bits2h(hh2[f]), bits2h(wp2h[512 + i2]),  u);
            u = __hfma2(bits2h(mh2[f]), bits2h(wp2h[1024 + i2]), u);
            u = __hfma2(bits2h(lh2[f]), bits2h(wp2h[1536 + i2]), u);
            u = __hfma2(bits2h(eh2[f]), bits2h(wp2h[2048 + i2]), u);
            u = __hmul2(__hmax2(u, zero2), bits2h(msh2[f]));
            X2u[(size_t)n * 512 + i2] = h2bits(u);
        }
        __syncthreads();
    }
}

// ---------------- fp32 -> fp16 convert and gather ----------------
__global__ void __launch_bounds__(256) convert_kernel(
    const float* __restrict__ src, __half* __restrict__ dst, int n)
{
    int i = blockIdx.x * 256 + threadIdx.x;
    if (i < n) dst[i] = __float2half(src[i]);
}

__global__ void __launch_bounds__(256) gather_kernel(
    const float* __restrict__ h, const int* __restrict__ i_obs,
    __half* __restrict__ dst)
{
    int n = blockIdx.x, t = threadIdx.x;
    int idx = i_obs[n];
    dst[(size_t)n * H + t] = __float2half(h[(size_t)idx * H + t]);
}

// ---------------- Kernel 2: HMMA fp16 GEMM, BM=128 BN=64, 2 CTAs/SM no-spill ----------------
#define BM 128
#define BN 64
#define BKB 32
#define PITCH 80
#define STAGE_A (BM * PITCH)              // 10240
#define STAGE_B (BN * PITCH)              // 5120
#define STAGE_BYTES (STAGE_A + STAGE_B)   // 15360
#define NSTAGE 4
#define GEMM_SMEM (NSTAGE * STAGE_BYTES)  // 61440; x2 CTAs = 122880 <= 228KB

__device__ __forceinline__ void cp16(uint32_t dst, const void* src, bool pred) {
    asm volatile("cp.async.cg.shared.global [%0], [%1], 16, %2;"
                 :: "r"(dst), "l"(src), "r"(pred ? 16 : 0));
}
__device__ __forceinline__ void ldm_x4(uint32_t* r, uint32_t addr) {
    asm volatile("ldmatrix.sync.aligned.m8n8.x4.shared.b16 {%0,%1,%2,%3}, [%4];"
                 : "=r"(r[0]), "=r"(r[1]), "=r"(r[2]), "=r"(r[3]) : "r"(addr));
}
__device__ __forceinline__ void mma16816(float* c, const uint32_t* a, uint32_t b0, uint32_t b1) {
    asm volatile("mma.sync.aligned.m16n8k16.row.col.f32.f16.f16.f32 "
                 "{%0,%1,%2,%3}, {%4,%5,%6,%7}, {%8,%9}, {%0,%1,%2,%3};"
                 : "+f"(c[0]), "+f"(c[1]), "+f"(c[2]), "+f"(c[3])
                 : "r"(a[0]), "r"(a[1]), "r"(a[2]), "r"(a[3]), "r"(b0), "r"(b1));
}

__global__ void __launch_bounds__(256, 2) mma_gemm(
    const __half* __restrict__ A, const __half* __restrict__ B,
    const float* __restrict__ bias, __half* __restrict__ C,
    int M, int K, int ldc)
{
    extern __shared__ char smem_raw[];
    const uint32_t su = smem_u32(smem_raw);

    const int t    = threadIdx.x;
    const int wid  = t >> 5;
    const int lane = t & 31;
    const int bm   = blockIdx.y * BM;
    const int bn   = blockIdx.x * BN;
    const int nk   = K / BKB;

    // 8 warps: 4 (M) x 2 (N); warp tile 32x32
    const int wm = (wid & 3) * 32;
    const int wn = (wid >> 2) * 32;

    const int rowt  = t >> 2;       // 0..63
    const int chunk = t & 3;

    const int garow0 = bm + rowt, garow1 = bm + rowt + 64;
    const bool p0 = garow0 < M, p1 = garow1 < M;
    const __half* A0 = A + (size_t)(p0 ? garow0 : 0) * K + chunk * 8;
    const __half* A1 = A + (size_t)(p1 ? garow1 : 0) * K + chunk * 8;
    const __half* B0 = B + (size_t)(bn + rowt) * K + chunk * 8;

    const uint32_t d0 = (uint32_t)rowt * PITCH + (uint32_t)chunk * 16;
    const uint32_t d1 = d0 + 64 * PITCH;

    auto load_stage = [&](int kb, int buf) {
        const uint32_t base = su + buf * STAGE_BYTES;
        const int ke = kb * BKB;
        cp16(base + d0,           A0 + ke, p0);
        cp16(base + d1,           A1 + ke, p1);
        cp16(base + STAGE_A + d0, B0 + ke, true);
    };

    float acc[2][4][4];
    #pragma unroll
    for (int i = 0; i < 2; i++)
        #pragma unroll
        for (int j = 0; j < 4; j++)
            #pragma unroll
            for (int k = 0; k < 4; k++) acc[i][j][k] = 0.0f;

    load_stage(0, 0); asm volatile("cp.async.commit_group;");
    load_stage(1, 1); asm volatile("cp.async.commit_group;");
    load_stage(2, 2); asm volatile("cp.async.commit_group;");

    int buf = 0;
    for (int kb = 0; kb < nk; kb++) {
        // uniform protocol: exactly one commit per iter (possibly empty);
        // pending is always 3 before the wait -> wait_group 2 retires stage kb
        asm volatile("cp.async.wait_group 2;");
        __syncthreads();

        const uint32_t sa = su + buf * STAGE_BYTES;
        const uint32_t sb = sa + STAGE_A;

        if (kb + 3 < nk) {
            int lbuf = buf + 3; if (lbuf >= NSTAGE) lbuf -= NSTAGE;
            load_stage(kb + 3, lbuf);
        }
        asm volatile("cp.async.commit_group;");

        #pragma unroll
        for (int ks = 0; ks < 2; ks++) {
            const uint32_t kbyte = (uint32_t)ks * 32;
            uint32_t a_r[2][4];
            const uint32_t arow = (uint32_t)(wm + (lane & 15)) * PITCH
                                + kbyte + ((uint32_t)(lane >> 4) << 4);
            #pragma unroll
            for (int mf = 0; mf < 2; mf++)
                ldm_x4(a_r[mf], sa + arow + (uint32_t)mf * 16 * PITCH);

            uint32_t b_r[2][4];
            const uint32_t brow = (uint32_t)(wn + (((lane >> 3) & 2) << 2) + (lane & 7)) * PITCH
                                + kbyte + (((uint32_t)(lane >> 3) & 1) << 4);
            #pragma unroll
            for (int nfp = 0; nfp < 2; nfp++)
                ldm_x4(b_r[nfp], sb + brow + (uint32_t)nfp * 16 * PITCH);

            #pragma unroll
            for (int mf = 0; mf < 2; mf++)
                #pragma unroll
                for (int nf = 0; nf < 4; nf++) {
                    const int nfp = nf >> 1, sub = (nf & 1) * 2;
                    mma16816(acc[mf][nf], a_r[mf], b_r[nfp][sub], b_r[nfp][sub + 1]);
                }
        }
        buf = buf + 1; if (buf >= NSTAGE) buf -= NSTAGE;
    }

    #pragma unroll
    for (int mf = 0; mf < 2; mf++) {
        const int r0 = bm + wm + mf * 16 + (lane >> 2);
        #pragma unroll
        for (int nf = 0; nf < 4; nf++) {
            const int col = bn + wn + nf * 8 + (lane & 3) * 2;
            const float b0 = bias[col], b1 = bias[col + 1];
            if (r0 < M)
                *(__half2*)(C + (size_t)r0 * ldc + col) =
                    __floats2half2_rn(acc[mf][nf][0] + b0, acc[mf][nf][1] + b1);
            if (r0 + 8 < M)
                *(__half2*)(C + (size_t)(r0 + 8) * ldc + col) =
                    __floats2half2_rn(acc[mf][nf][2] + b0, acc[mf][nf][3] + b1);
        }
    }
}

// ---------------- Kernel 3: GRU gates + MLP head, half2 math ----------------
#define GR 16
#define GW1H 0
#define GW3H (GW1H + 32 * 256)
#define GW2S (GW3H + 256 * 17)
#define GZIN (GW2S + 32 * 33)
#define GZ1  (GZIN + 256)
#define GZ2H (GZ1 + 32)
#define GB1S (GZ2H + 16)
#define GB2S (GB1S + 32)
#define GB3S (GB2S + 32)
#define GATES_SMEM ((GB3S + 256) * 4)

__global__ void __launch_bounds__(256) gates_mlp_kernel(
    const float* __restrict__ h, const int* __restrict__ i_obs,
    const float* __restrict__ m_w1, const float* __restrict__ m_b1,
    const float* __restrict__ m_w2, const float* __restrict__ m_b2,
    const float* __restrict__ m_w3, const float* __restrict__ m_b3,
    float* __restrict__ out_h)
{
    extern __shared__ uint32_t smu[];
    uint32_t* w1h = smu + GW1H;
    uint32_t* w3h = smu + GW3H;
    float*    w2s = (float*)(smu + GW2S);
    uint32_t* zin = smu + GZIN;
    __half*   zin_h = (__half*)zin;
    float*    z1  = (float*)(smu + GZ1);
    __half*   z2h = (__half*)(smu + GZ2H);
    uint32_t* z2u = smu + GZ2H;
    float*    b1s = (float*)(smu + GB1S);
    float*    b2s = (float*)(smu + GB2S);
    float*    b3s = (float*)(smu + GB3S);

    const int t    = threadIdx.x;
    const int wid  = t >> 5;
    const int lane = t & 31;

    for (int i = t; i < 32 * 256; i += 256)
        w1h[i] = h2bits(__floats2half2_rn(m_w1[2 * i], m_w1[2 * i + 1]));
    for (int i = t; i < 256 * 16; i += 256) {
        int o = i >> 4, k = i & 15;
        w3h[o * 17 + k] = h2bits(__floats2half2_rn(m_w3[2 * i], m_w3[2 * i + 1]));
    }
    for (int i = t; i < 32 * 32; i += 256)
        w2s[(i >> 5) * 33 + (i & 31)] = m_w2[i];
    if (t < 32) { b1s[t] = m_b1[t]; b2s[t] = m_b2[t]; }
    for (int i = t; i < 256; i += 256) b3s[i] = m_b3[i];
    __syncthreads();

    const int n0 = blockIdx.x * GR;
    for (int r = 0; r < GR; r++) {
        const int n = n0 + r;
        const int idx = i_obs[n];
        const size_t b  = (size_t)n * G3;
        const size_t bh = (size_t)n * G6;

        const float hg = h[(size_t)idx * H + t];
        {
            float gi0 = __half2float(g_GI1[b + t]);
            float gi1 = __half2float(g_GI1[b + H + t]);
            float gi2 = __half2float(g_GI1[b + 2 * H + t]);
            float gh0 = __half2float(g_GH12[bh + t]);
            float gh1 = __half2float(g_GH12[bh + H + t]);
            float gh2 = __half2float(g_GH12[bh + 2 * H + t]);
            float rr = sigmoidf_(gi0 + gh0);
            float zz = sigmoidf_(gi1 + gh1);
            float ng = tanhf(gi2 + rr * gh2);
            zin_h[t] = __float2half((1.0f - zz) * ng + zz * hg);
        }
        {
            float gi0 = __half2float(g_GI2[b + t]);
            float gi1 = __half2float(g_GI2[b + H + t]);
            float gi2 = __half2float(g_GI2[b + 2 * H + t]);
            float gh0 = __half2float(g_GH12[bh + G3 + t]);
            float gh1 = __half2float(g_GH12[bh + G3 + H + t]);
            float gh2 = __half2float(g_GH12[bh + G3 + 2 * H + t]);
            float rr = sigmoidf_(gi0 + gh0);
            float zz = sigmoidf_(gi1 + gh1);
            float ng = tanhf(gi2 + rr * gh2);
            zin_h[256 + t] = __float2half((1.0f - zz) * ng + zz * hg);
        }
        __syncthreads();

        uint32_t zr[8];
        #pragma unroll
        for (int j = 0; j < 8; j++) zr[j] = zin[lane + 32 * j];
        #pragma unroll
        for (int q = 0; q < 4; q++) {
            const int o = 4 * wid + q;
            const uint32_t* wr = w1h + o * 256;
            __half2 s2 = __float2half2_rn(0.0f);
            #pragma unroll
            for (int j = 0; j < 8; j++)
                s2 = __hfma2(bits2h(wr[lane + 32 * j]), bits2h(zr[j]), s2);
            #pragma unroll
            for (int off = 16; off > 0; off >>= 1)
                s2 = __hadd2(s2, shfl_xor_h2(s2, off));
            if (lane == 0) {
                float s = __low2float(s2) + __high2float(s2) + b1s[o];
                z1[o] = fmaxf(s, 0.0f);
            }
        }
        __syncthreads();

        if (t < 32) {
            const float* w = w2s + t * 33;
            float s = b2s[t];
            #pragma unroll
            for (int k = 0; k < 32; k++) s = fmaf(z1[k], w[k], s);
            z2h[t] = __float2half(fmaxf(s, 0.0f));
        }
        __syncthreads();

        {
            const uint32_t* wr = w3h + t * 17;
            __half2 s2 = __float2half2_rn(0.0f);
            #pragma unroll
            for (int k = 0; k < 16; k++)
                s2 = __hfma2(bits2h(wr[k]), bits2h(z2u[k]), s2);
            float s = __low2float(s2) + __high2float(s2) + b3s[t];
            out_h[(size_t)idx * H + t] = s * sigmoidf_(s);
        }
        __syncthreads();
    }
}

// ---------------- launch ----------------
extern "C" void kernel_launch(void* const* d_in, const int* in_sizes, int n_in,
                              void* d_out, int out_size)
{
    const float* h         = (const float*)d_in[0];
    const float* p_obs     = (const float*)d_in[1];
    const float* X_obs     = (const float*)d_in[2];
    const float* M_obs     = (const float*)d_in[3];
    const float* adj       = (const float*)d_in[4];
    const int*   i_obs     = (const int*)  d_in[5];
    const float* w_prep    = (const float*)d_in[6];
    const float* w_prep2   = (const float*)d_in[7];
    const float* bias_prep = (const float*)d_in[8];
    const float* g1_w_ih   = (const float*)d_in[9];
    const float* g1_w_hh   = (const float*)d_in[10];
    const float* g1_b_ih   = (const float*)d_in[11];
    const float* g1_b_hh   = (const float*)d_in[12];
    const float* g2_w_ih   = (const float*)d_in[13];
    const float* g2_w_hh   = (const float*)d_in[14];
    const float* g2_b_ih   = (const float*)d_in[15];
    const float* g2_b_hh   = (const float*)d_in[16];
    const float* gcn_w1    = (const float*)d_in[17];
    const float* gcn_b1    = (const float*)d_in[18];
    const float* gcn_w2    = (const float*)d_in[19];
    const float* gcn_b2    = (const float*)d_in[20];
    const float* m_w1      = (const float*)d_in[21];
    const float* m_b1      = (const float*)d_in[22];
    const float* m_w2      = (const float*)d_in[23];
    const float* m_b2      = (const float*)d_in[24];
    const float* m_w3      = (const float*)d_in[25];
    const float* m_b3      = (const float*)d_in[26];

    float* out_h      = (float*)d_out;                           // [100000,256]
    float* out_losses = (float*)d_out + (size_t)N_TOTAL * H;     // [50000,64]

    cudaMemcpyAsync(out_h, h, (size_t)N_TOTAL * H * sizeof(float),
                    cudaMemcpyDeviceToDevice, 0);

    __half *pX1, *pX2, *pHg, *pW1ih, *pW2ih, *pWhh, *pGI1, *pGI2, *pGH12;
    float *pbhh;
    cudaGetSymbolAddress((void**)&pX1, g_X1);
    cudaGetSymbolAddress((void**)&pX2, g_X2);
    cudaGetSymbolAddress((void**)&pHg, g_Hg);
    cudaGetSymbolAddress((void**)&pW1ih, g_W1ih);
    cudaGetSymbolAddress((void**)&pW2ih, g_W2ih);
    cudaGetSymbolAddress((void**)&pWhh, g_Whh);
    cudaGetSymbolAddress((void**)&pGI1, g_GI1);
    cudaGetSymbolAddress((void**)&pGI2, g_GI2);
    cudaGetSymbolAddress((void**)&pGH12, g_GH12);
    cudaGetSymbolAddress((void**)&pbhh, g_bhh);

    cudaMemcpyAsync(pbhh,      g1_b_hh, G3 * sizeof(float), cudaMemcpyDeviceToDevice, 0);
    cudaMemcpyAsync(pbhh + G3, g2_b_hh, G3 * sizeof(float), cudaMemcpyDeviceToDevice, 0);

    gather_kernel<<<N_OBS, 256>>>(h, i_obs, pHg);
    convert_kernel<<<(G3 * H + 255) / 256, 256>>>(g1_w_hh, pWhh, G3 * H);
    convert_kernel<<<(G3 * H + 255) / 256, 256>>>(g2_w_hh, pWhh + (size_t)G3 * H, G3 * H);

    cudaFuncSetAttribute(mma_gemm, cudaFuncAttributeMaxDynamicSharedMemorySize, GEMM_SMEM);

    dim3 gg_ih(G3 / BN, (N_OBS + BM - 1) / BM);
    dim3 gg_hh(G6 / BN, (N_OBS + BM - 1) / BM);
    mma_gemm<<<gg_hh, 256, GEMM_SMEM>>>(pHg, pWhh, pbhh, pGH12, N_OBS, H, G6);

    cudaFuncSetAttribute(prep_kernel, cudaFuncAttributeMaxDynamicSharedMemorySize, PREP_SMEM);
    prep_kernel<<<N_OBS / PREP_ROWS, 256, PREP_SMEM>>>(
        p_obs, X_obs, M_obs, adj, w_prep, w_prep2, bias_prep,
        gcn_w1, gcn_b1, gcn_w2, gcn_b2, out_losses);

    convert_kernel<<<(G3 * XK + 255) / 256, 256>>>(g1_w_ih, pW1ih, G3 * XK);
    convert_kernel<<<(G3 * XK + 255) / 256, 256>>>(g2_w_ih, pW2ih, G3 * XK);

    mma_gemm<<<gg_ih, 256, GEMM_SMEM>>>(pX1, pW1ih, g1_b_ih, pGI1, N_OBS, XK, G3);
    mma_gemm<<<gg_ih, 256, GEMM_SMEM>>>(pX2, pW2ih, g2_b_ih, pGI2, N_OBS, XK, G3);

    cudaFuncSetAttribute(gates_mlp_kernel, cudaFuncAttributeMaxDynamicSharedMemorySize, GATES_SMEM);
    gates_mlp_kernel<<<N_OBS / GR, 256, GATES_SMEM>>>(h, i_obs, m_w1, m_b1, m_w2, m_b2,
                                                      m_w3, m_b3, out_h);
}